// round 5
// baseline (speedup 1.0000x reference)
#include <cuda_runtime.h>

// INLWT inverse lifting wavelet transform — fused one-pass, float4-vectorized,
// 2 output row-pairs per thread. A thread handling rows (i, i+1) loads input
// rows (i-1, i, i+1): row i serves as "cur" for row i and "up" for row i+1,
// cutting global loads by 25% vs one-row-per-thread. j-1 terms flow through
// registers + __shfl_up; lane 0 reloads the warp-boundary pixel.

#define H1 256
#define W1 256

__device__ __forceinline__ void lift_cur(const float4& a, const float4& b,
                                         const float4& c, const float4& d,
                                         float y0[4], float r2[4])
{
    const float ax[4] = {a.x, a.y, a.z, a.w};
    const float bx[4] = {b.x, b.y, b.z, b.w};
    const float cx[4] = {c.x, c.y, c.z, c.w};
    const float dx[4] = {d.x, d.y, d.z, d.w};
    #pragma unroll
    for (int p = 0; p < 4; ++p) {
        y0[p] = 1.3066f * ax[p] + (-0.5412f) * bx[p] + (-0.4671f) * cx[p] +  1.3349f * dx[p];
        r2[p] = 0.5412f * ax[p] +   1.3066f  * bx[p] +   1.3349f  * cx[p] +  0.4671f * dx[p];
    }
}

__device__ __forceinline__ void lift_up(const float4& a, const float4& b,
                                        const float4& c, const float4& d,
                                        float y1[4], float r3[4])
{
    const float ax[4] = {a.x, a.y, a.z, a.w};
    const float bx[4] = {b.x, b.y, b.z, b.w};
    const float cx[4] = {c.x, c.y, c.z, c.w};
    const float dx[4] = {d.x, d.y, d.z, d.w};
    #pragma unroll
    for (int p = 0; p < 4; ++p) {
        y1[p] = 0.5412f * ax[p] +   1.3066f  * bx[p] + (-1.3349f) * cx[p] + (-0.4671f) * dx[p];
        r3[p] = 1.3066f * ax[p] + (-0.5412f) * bx[p] +   0.4671f  * cx[p] + (-1.3349f) * dx[p];
    }
}

__device__ __forceinline__ void emit_rows(float* __restrict__ orow0,
                                          float* __restrict__ orow1,
                                          const float y0[4], const float y1[4],
                                          const float r2[4], const float r3[4],
                                          float r2m, float r3m)
{
    float z0[4], z1[4], z2[4], z3[4];
    #pragma unroll
    for (int p = 0; p < 4; ++p) {
        const float v2 = (p == 0) ? r2m : r2[p - 1];
        const float v3 = (p == 0) ? r3m : r3[p - 1];
        z0[p] =   0.2281f  * y0[p] +   0.0064f  * y1[p] + (-0.1021f) * v2 +   0.0029f  * v3;
        z1[p] = (-0.0064f) * y0[p] +   0.2281f  * y1[p] +   0.0029f  * v2 +   0.1021f  * v3;
        z2[p] =   0.1021f  * y0[p] +   0.0029f  * y1[p] +   0.2281f  * v2 + (-0.0064f) * v3;
        z3[p] =   0.0029f  * y0[p] + (-0.1021f) * y1[p] +   0.0064f  * v2 +   0.2281f  * v3;
    }
    reinterpret_cast<float4*>(orow0)[0] = make_float4(z0[0], z1[0], z0[1], z1[1]);
    reinterpret_cast<float4*>(orow0)[1] = make_float4(z0[2], z1[2], z0[3], z1[3]);
    reinterpret_cast<float4*>(orow1)[0] = make_float4(z2[0], z3[0], z2[1], z3[1]);
    reinterpret_cast<float4*>(orow1)[1] = make_float4(z2[2], z3[2], z2[3], z3[3]);
}

__global__ void __launch_bounds__(256) inlwt_kernel(
    const float* __restrict__ A,
    const float* __restrict__ B,
    const float* __restrict__ C,
    const float* __restrict__ D,
    float* __restrict__ out)
{
    const int tid  = threadIdx.x;
    const int rowb = tid >> 6;            // 0..3 : row-pair within block
    const int x    = tid & 63;            // 0..63 : pixel-group within row
    const int lane = tid & 31;

    const int i0 = blockIdx.x * 8 + rowb * 2;   // even, 0..254; thread does i0, i0+1
    const int i1 = i0 + 1;
    const int bc = blockIdx.y;

    const size_t plane = (size_t)H1 * W1;
    const size_t base  = (size_t)bc * plane;

    const int im1 = (i0 == 0) ? (H1 - 1) : (i0 - 1);
    const int j0  = x << 2;

    const size_t oU = base + (size_t)im1 * W1 + j0;   // row i0-1
    const size_t o0 = base + (size_t)i0  * W1 + j0;   // row i0
    const size_t o1 = base + (size_t)i1  * W1 + j0;   // row i0+1

    // 12 x LDG.128 — fully coalesced, MLP=12 per thread.
    const float4 aU = *reinterpret_cast<const float4*>(A + oU);
    const float4 bU = *reinterpret_cast<const float4*>(B + oU);
    const float4 cU = *reinterpret_cast<const float4*>(C + oU);
    const float4 dU = *reinterpret_cast<const float4*>(D + oU);
    const float4 a0 = *reinterpret_cast<const float4*>(A + o0);
    const float4 b0 = *reinterpret_cast<const float4*>(B + o0);
    const float4 c0 = *reinterpret_cast<const float4*>(C + o0);
    const float4 d0 = *reinterpret_cast<const float4*>(D + o0);
    const float4 a1 = *reinterpret_cast<const float4*>(A + o1);
    const float4 b1 = *reinterpret_cast<const float4*>(B + o1);
    const float4 c1 = *reinterpret_cast<const float4*>(C + o1);
    const float4 d1 = *reinterpret_cast<const float4*>(D + o1);

    // Lifting combos. Row i0 data feeds both its own cur-combos and the
    // up-combos of row i1 — the 25% load saving.
    float y0a[4], r2a[4], y1a[4], r3a[4];   // output row-pair at i0
    float y0b[4], r2b[4], y1b[4], r3b[4];   // output row-pair at i1
    lift_cur(a0, b0, c0, d0, y0a, r2a);
    lift_up (aU, bU, cU, dU, y1a, r3a);
    lift_cur(a1, b1, c1, d1, y0b, r2b);
    lift_up (a0, b0, c0, d0, y1b, r3b);

    // Neighbor pixel (j0-1) combos: shfl from lane-1; lane 0 reloads boundary.
    float r2ma = __shfl_up_sync(0xFFFFFFFFu, r2a[3], 1);
    float r3ma = __shfl_up_sync(0xFFFFFFFFu, r3a[3], 1);
    float r2mb = __shfl_up_sync(0xFFFFFFFFu, r2b[3], 1);
    float r3mb = __shfl_up_sync(0xFFFFFFFFu, r3b[3], 1);
    if (lane == 0) {
        const int jm1 = (j0 == 0) ? (W1 - 1) : (j0 - 1);
        const size_t pU = base + (size_t)im1 * W1 + jm1;
        const size_t p0 = base + (size_t)i0  * W1 + jm1;
        const size_t p1 = base + (size_t)i1  * W1 + jm1;
        const float au = A[pU], bu = B[pU], cu = C[pU], du = D[pU];
        const float a_ = A[p0], b_ = B[p0], c_ = C[p0], d_ = D[p0];
        const float av = A[p1], bv = B[p1], cv = C[p1], dv = D[p1];
        r2ma = 0.5412f * a_ +   1.3066f  * b_ + 1.3349f * c_ +   0.4671f  * d_;
        r3ma = 1.3066f * au + (-0.5412f) * bu + 0.4671f * cu + (-1.3349f) * du;
        r2mb = 0.5412f * av +   1.3066f  * bv + 1.3349f * cv +   0.4671f  * dv;
        r3mb = 1.3066f * a_ + (-0.5412f) * b_ + 0.4671f * c_ + (-1.3349f) * d_;
    }

    // Second lifting stage + 2x2 depth-to-space. 8 x STG.128 total.
    const int W = 2 * W1;
    float* obase = out + (size_t)bc * (2 * H1) * W + 2 * j0;
    emit_rows(obase + (size_t)(2 * i0)     * W,
              obase + (size_t)(2 * i0 + 1) * W,
              y0a, y1a, r2a, r3a, r2ma, r3ma);
    emit_rows(obase + (size_t)(2 * i1)     * W,
              obase + (size_t)(2 * i1 + 1) * W,
              y0b, y1b, r2b, r3b, r2mb, r3mb);
}

extern "C" void kernel_launch(void* const* d_in, const int* in_sizes, int n_in,
                              void* d_out, int out_size)
{
    const float* A = (const float*)d_in[0];
    const float* B = (const float*)d_in[1];
    const float* C = (const float*)d_in[2];
    const float* D = (const float*)d_in[3];
    float* out = (float*)d_out;

    const int bc = in_sizes[0] / (H1 * W1);  // b*c

    dim3 grid(H1 / 8, bc);   // block covers 8 rows (4 row-pairs) of one plane
    dim3 block(256);
    inlwt_kernel<<<grid, block>>>(A, B, C, D, out);
}